// round 12
// baseline (speedup 1.0000x reference)
#include <cuda_runtime.h>
#include <cuda_fp16.h>
#include <cstdint>
#include <stdint.h>
#include <math.h>

// Problem constants (fixed by the dataset)
#define TSEQ   2048
#define DDIM   4096
#define NQ     32
#define NKV    8
#define HD     128
#define NSLOTS 32768
#define QKVC   6144   // 32*128 + 8*128 + 8*128

// Packed-weight offsets (uint = half2 elements), pack along K
#define WQP_ELEMS ((size_t)NQ  * (DDIM / 2) * HD)
#define WKP_ELEMS ((size_t)NKV * (DDIM / 2) * HD)
#define WOP_ELEMS ((size_t)(DDIM / 2) * DDIM)
#define WQP_OFF   ((size_t)0)
#define WKP_OFF   (WQP_OFF + WQP_ELEMS)
#define WVP_OFF   (WKP_OFF + WKP_ELEMS)
#define WOP_OFF   (WVP_OFF + WKP_ELEMS)

// ---------------- scratch (static device allocations; no cudaMalloc) -------
__device__ float    g_QKV[(size_t)TSEQ * QKVC];      // [t][6144] fp32
__device__ __half   g_Qh [(size_t)NQ  * TSEQ * HD];  // [n][t][h] fp16 (scaled)
__device__ __half   g_Kh [(size_t)NKV * TSEQ * HD];  // [kh][t][h] fp16
__device__ unsigned g_Vp [(size_t)NKV * (TSEQ / 2) * HD]; // key-pair half2
__device__ __half   g_A2h[(size_t)TSEQ * DDIM];      // [t][n*128+h] fp16
__device__ __half   g_Xh [(size_t)TSEQ * DDIM];      // x fp16 (A-side)
__device__ unsigned g_Wp [WOP_OFF + WOP_ELEMS];      // packed half2 weights

// ---------------- mma helpers -----------------------------------------------
__device__ __forceinline__ void mma_f16(float* d, const unsigned* a,
                                        const unsigned* b) {
    asm volatile(
        "mma.sync.aligned.m16n8k16.row.col.f32.f16.f16.f32 "
        "{%0,%1,%2,%3}, {%4,%5,%6,%7}, {%8,%9}, {%0,%1,%2,%3};"
        : "+f"(d[0]), "+f"(d[1]), "+f"(d[2]), "+f"(d[3])
        : "r"(a[0]), "r"(a[1]), "r"(a[2]), "r"(a[3]), "r"(b[0]), "r"(b[1]));
}

// fp16-accumulator variant: D/C are 2 regs (4 halves), chained in-place
__device__ __forceinline__ void mma_f16acc(unsigned* d, const unsigned* a,
                                           const unsigned* b) {
    asm volatile(
        "mma.sync.aligned.m16n8k16.row.col.f16.f16.f16.f16 "
        "{%0,%1}, {%2,%3,%4,%5}, {%6,%7}, {%0,%1};"
        : "+r"(d[0]), "+r"(d[1])
        : "r"(a[0]), "r"(a[1]), "r"(a[2]), "r"(a[3]), "r"(b[0]), "r"(b[1]));
}

__device__ __forceinline__ void cp16(unsigned smem, const void* g) {
    asm volatile("cp.async.cg.shared.global [%0], [%1], 16;\n"
                 :: "r"(smem), "l"(g));
}

__device__ __forceinline__ unsigned pack_h2(float a, float b) {
    __half2 h = __floats2half2_rn(a, b);
    return *(unsigned*)&h;
}

// ---------------- prep kernels ---------------------------------------------
__global__ __launch_bounds__(256) void k_cvt_half(
    const float4* __restrict__ in, uint2* __restrict__ out, int n4)
{
    int i = blockIdx.x * 256 + threadIdx.x;
    if (i < n4) {
        float4 v = in[i];
        uint2 o = {pack_h2(v.x, v.y), pack_h2(v.z, v.w)};
        out[i] = o;
    }
}

__global__ __launch_bounds__(256) void k_pack_half(
    const float* __restrict__ in, unsigned* __restrict__ out, int K2, int N)
{
    int i = blockIdx.x * 256 + threadIdx.x;
    if (i < K2 * N) {
        int k2 = i / N, n = i - k2 * N;
        out[i] = pack_h2(in[(size_t)(2 * k2) * N + n],
                         in[(size_t)(2 * k2 + 1) * N + n]);
    }
}

// ---------------- 128x128 fp16 GEMM, 4 warps, 64x64 warp tile --------------
// fp16-accumulator MMA chained over one BK=32 stage (K=32 window), promoted
// to fp32 register accumulators at each stage boundary.
__device__ __forceinline__ void gemm_mma128_h(
    const __half* __restrict__ A, int lda,
    const unsigned* __restrict__ Bp, int ldbp,
    float* __restrict__ C, int ldc,
    int Kdim, int rowBase)
{
    __shared__ unsigned As[3][128][20];
    __shared__ unsigned Bs[3][16][136];

    const int tid  = threadIdx.x;
    const int lane = tid & 31;
    const int warp = tid >> 5;
    const int wM   = warp >> 1;
    const int wN   = warp & 1;
    const int g    = lane >> 2;
    const int t    = lane & 3;

    const int ar = tid >> 2, ac = (tid & 3) << 2;
    const int br = tid >> 5, bc = (tid & 31) << 2;

    const __half* Ab = A + (size_t)rowBase * lda;

    float acc[4][8][4];
#pragma unroll
    for (int mt = 0; mt < 4; mt++)
#pragma unroll
        for (int nt = 0; nt < 8; nt++)
#pragma unroll
            for (int i = 0; i < 4; i++) acc[mt][nt][i] = 0.f;

    const unsigned sA0 = (unsigned)__cvta_generic_to_shared(&As[0][0][0]);
    const unsigned sB0 = (unsigned)__cvta_generic_to_shared(&Bs[0][0][0]);
    const unsigned stASz = (unsigned)(128 * 20 * 4);
    const unsigned stBSz = (unsigned)(16 * 136 * 4);

    const int niter = Kdim >> 5;

#pragma unroll
    for (int p = 0; p < 2; p++) {
        const int k0 = p << 5;
        const int k20 = k0 >> 1;
        const unsigned stA = sA0 + (unsigned)p * stASz;
        const unsigned stB = sB0 + (unsigned)p * stBSz;
#pragma unroll
        for (int q = 0; q < 4; q++) {
            cp16(stA + (unsigned)((ar + q * 32) * 20 + ac) * 4u,
                 Ab + (size_t)(ar + q * 32) * lda + k0 + ac * 2);
            cp16(stB + (unsigned)((br + q * 4) * 136 + bc) * 4u,
                 Bp + (size_t)(k20 + br + q * 4) * ldbp + bc);
        }
        asm volatile("cp.async.commit_group;");
    }

    for (int it = 0; it < niter; it++) {
        asm volatile("cp.async.wait_group 1;");
        __syncthreads();

        if (it + 2 < niter) {
            const int k0 = (it + 2) << 5;
            const int k20 = k0 >> 1;
            const int bsel = (it + 2) % 3;
            const unsigned stA = sA0 + (unsigned)bsel * stASz;
            const unsigned stB = sB0 + (unsigned)bsel * stBSz;
#pragma unroll
            for (int q = 0; q < 4; q++) {
                cp16(stA + (unsigned)((ar + q * 32) * 20 + ac) * 4u,
                     Ab + (size_t)(ar + q * 32) * lda + k0 + ac * 2);
                cp16(stB + (unsigned)((br + q * 4) * 136 + bc) * 4u,
                     Bp + (size_t)(k20 + br + q * 4) * ldbp + bc);
            }
        }
        asm volatile("cp.async.commit_group;");

        const int st = it % 3;
#pragma unroll
        for (int mt = 0; mt < 4; mt++) {
            // A fragments for both K16 substeps of this stage
            const unsigned* p0 = &As[st][wM * 64 + mt * 16 + g][t];
            unsigned af0[4] = {p0[0], p0[8 * 20], p0[4], p0[8 * 20 + 4]};
            const unsigned* p1 = p0 + 8;
            unsigned af1[4] = {p1[0], p1[8 * 20], p1[4], p1[8 * 20 + 4]};
#pragma unroll
            for (int nt = 0; nt < 8; nt++) {
                const int col = wN * 64 + nt * 8 + g;
                unsigned b0[2] = {Bs[st][t][col],     Bs[st][t + 4][col]};
                unsigned b1[2] = {Bs[st][8 + t][col], Bs[st][8 + t + 4][col]};
                unsigned d[2] = {0u, 0u};
                mma_f16acc(d, af0, b0);
                mma_f16acc(d, af1, b1);
                float2 lo = __half22float2(*(__half2*)&d[0]);
                float2 hi = __half22float2(*(__half2*)&d[1]);
                acc[mt][nt][0] += lo.x; acc[mt][nt][1] += lo.y;
                acc[mt][nt][2] += hi.x; acc[mt][nt][3] += hi.y;
            }
        }
    }

#pragma unroll
    for (int mt = 0; mt < 4; mt++) {
#pragma unroll
        for (int nt = 0; nt < 8; nt++) {
            const int r0 = rowBase + wM * 64 + mt * 16 + g;
            const int c0 = wN * 64 + nt * 8 + 2 * t;
            float2 v0 = {acc[mt][nt][0], acc[mt][nt][1]};
            float2 v1 = {acc[mt][nt][2], acc[mt][nt][3]};
            *(float2*)(C + (size_t)r0 * ldc + c0)       = v0;
            *(float2*)(C + (size_t)(r0 + 8) * ldc + c0) = v1;
        }
    }
}

// ---------------- kernel 1: fused QKV projection ---------------------------
__global__ __launch_bounds__(128) void k_gemm_qkv()
{
    int cb = blockIdx.x;
    const unsigned* Bp;
    if (cb < 32)      Bp = g_Wp + WQP_OFF + (size_t)cb * (DDIM / 2) * HD;
    else if (cb < 40) Bp = g_Wp + WKP_OFF + (size_t)(cb - 32) * (DDIM / 2) * HD;
    else              Bp = g_Wp + WVP_OFF + (size_t)(cb - 40) * (DDIM / 2) * HD;
    gemm_mma128_h(g_Xh, DDIM, Bp, HD, g_QKV + (size_t)cb * HD, QKVC,
                  DDIM, blockIdx.y * 128);
}

// ---------------- kernel 2: RoPE + fp16 split + cache writeback ------------
__global__ __launch_bounds__(256) void k_rope(
    const int* __restrict__ positions,
    const int* __restrict__ widx,
    float* __restrict__ out_kc,
    float* __restrict__ out_vc)
{
    const int t = blockIdx.x;
    __shared__ float cs[64], sn[64];
    const int pos = positions[t];
    if (threadIdx.x < 64) {
        int i = threadIdx.x;
        double e = -((double)(2 * i) / 128.0);
        float inv = (float)pow(500000.0, e);
        float ang = (float)pos * inv;
        float s, c;
        sincosf(ang, &s, &c);
        cs[i] = c;
        sn[i] = s;
    }
    __syncthreads();

    const float* row = g_QKV + (size_t)t * QKVC;
    const int wi = widx[t];
    const float qscale = 0.08838834764831845f;  // 128^-0.5

    for (int idx = threadIdx.x; idx < NQ * 64; idx += blockDim.x) {
        int n = idx >> 6, i = idx & 63;
        float x1 = row[n * HD + i];
        float x2 = row[n * HD + 64 + i];
        float c = cs[i], s = sn[i];
        __half* qd = g_Qh + ((size_t)n * TSEQ + t) * HD;
        qd[i]      = __float2half((x1 * c - x2 * s) * qscale);
        qd[64 + i] = __float2half((x2 * c + x1 * s) * qscale);
    }
    for (int idx = threadIdx.x; idx < NKV * 64; idx += blockDim.x) {
        int kh = idx >> 6, i = idx & 63;
        float x1 = row[NQ * HD + kh * HD + i];
        float x2 = row[NQ * HD + kh * HD + 64 + i];
        float c = cs[i], s = sn[i];
        float o1 = x1 * c - x2 * s;
        float o2 = x2 * c + x1 * s;
        __half* kd = g_Kh + ((size_t)kh * TSEQ + t) * HD;
        kd[i] = __float2half(o1); kd[64 + i] = __float2half(o2);
        float* kc = out_kc + ((size_t)wi * NKV + kh) * HD;
        kc[i] = o1; kc[64 + i] = o2;    // cache stays exact fp32
    }
    for (int idx = threadIdx.x; idx < NKV * HD; idx += blockDim.x) {
        int kh = idx >> 7, h = idx & 127;
        float v = row[(NQ + NKV) * HD + kh * HD + h];
        __half* vh = (__half*)g_Vp;
        vh[(((size_t)kh * (TSEQ / 2) + (t >> 1)) * HD + h) * 2 + (t & 1)] =
            __float2half(v);
        out_vc[((size_t)wi * NKV + kh) * HD + h] = v;   // exact fp32
    }
}

// ---------------- kernel 3: fp16-mma causal flash attention ----------------
#define ATTN3_SMEM_WORDS (4352 * 3 + 64)
__global__ __launch_bounds__(128) void k_attn_h(const int* __restrict__ positions)
{
    extern __shared__ unsigned smw[];
    unsigned* Qs  = smw;
    unsigned* Ks  = smw + 4352;
    unsigned* Vp  = smw + 8704;
    int*      PKs = (int*)(smw + 13056);
    unsigned* Ps  = Ks;               // alias (Ks dead once S is computed)

    const int n    = blockIdx.y;
    const int kh   = n >> 2;
    const int t0   = blockIdx.x * 64;
    const int tid  = threadIdx.x;
    const int lane = tid & 31;
    const int w    = tid >> 5;
    const int g    = lane >> 2;
    const int t    = lane & 3;

    const unsigned* Qg = (const unsigned*)(g_Qh + ((size_t)n * TSEQ + t0) * HD);
    for (int i = tid; i < 1024; i += 128) {
        int r = i >> 4, c = (i & 15) << 2;
        *(uint4*)(Qs + r * 68 + c) = *(const uint4*)(Qg + (size_t)r * 64 + c);
    }

    const int row0 = w * 16 + g;
    const int pq0 = positions[t0 + row0];
    const int pq1 = positions[t0 + row0 + 8];

    float m0 = -1e30f, m1 = -1e30f, l0 = 0.f, l1 = 0.f;
    float o[16][4];
#pragma unroll
    for (int nt = 0; nt < 16; nt++)
#pragma unroll
        for (int i = 0; i < 4; i++) o[nt][i] = 0.f;

    const unsigned* Kg = (const unsigned*)(g_Kh + (size_t)kh * TSEQ * HD);
    const unsigned* Vg = g_Vp + (size_t)kh * (TSEQ / 2) * HD;

    const int nchunks = blockIdx.x + 1;
    for (int ch = 0; ch < nchunks; ch++) {
        const int s0 = ch * 64;
        __syncthreads();

        for (int i = tid; i < 1024; i += 128) {
            int r = i >> 4, c = (i & 15) << 2;
            *(uint4*)(Ks + r * 68 + c) =
                *(const uint4*)(Kg + (size_t)(s0 + r) * 64 + c);
        }
        for (int i = tid; i < 1024; i += 128) {
            int r2 = i >> 5, c = (i & 31) << 2;
            *(uint4*)(Vp + r2 * 136 + c) =
                *(const uint4*)(Vg + (size_t)(s0 / 2 + r2) * HD + c);
        }
        if (tid < 64) PKs[tid] = positions[s0 + tid];
        __syncthreads();

        float s[8][4];
#pragma unroll
        for (int nt = 0; nt < 8; nt++)
#pragma unroll
            for (int i = 0; i < 4; i++) s[nt][i] = 0.f;

#pragma unroll
        for (int ks = 0; ks < 8; ks++) {
            const unsigned* qp = Qs + row0 * 68 + ks * 8;
            unsigned a[4] = {qp[t], qp[8 * 68 + t], qp[t + 4], qp[8 * 68 + t + 4]};
#pragma unroll
            for (int nt = 0; nt < 8; nt++) {
                const unsigned* kp = Ks + (nt * 8 + g) * 68 + ks * 8;
                unsigned bb[2] = {kp[t], kp[t + 4]};
                mma_f16(s[nt], a, bb);
            }
        }

        float mx0 = -1e30f, mx1 = -1e30f;
#pragma unroll
        for (int nt = 0; nt < 8; nt++) {
            const int col = nt * 8 + 2 * t;
            int2 pk = *(const int2*)(PKs + col);
            if (pq0 < pk.x) s[nt][0] = -1e30f;
            if (pq0 < pk.y) s[nt][1] = -1e30f;
            if (pq1 < pk.x) s[nt][2] = -1e30f;
            if (pq1 < pk.y) s[nt][3] = -1e30f;
            mx0 = fmaxf(mx0, fmaxf(s[nt][0], s[nt][1]));
            mx1 = fmaxf(mx1, fmaxf(s[nt][2], s[nt][3]));
        }
        mx0 = fmaxf(mx0, __shfl_xor_sync(0xffffffffu, mx0, 1));
        mx0 = fmaxf(mx0, __shfl_xor_sync(0xffffffffu, mx0, 2));
        mx1 = fmaxf(mx1, __shfl_xor_sync(0xffffffffu, mx1, 1));
        mx1 = fmaxf(mx1, __shfl_xor_sync(0xffffffffu, mx1, 2));

        const float mn0 = fmaxf(m0, mx0), mn1 = fmaxf(m1, mx1);
        const float c0 = __expf(m0 - mn0), c1 = __expf(m1 - mn1);
        m0 = mn0; m1 = mn1;

        float sum0 = 0.f, sum1 = 0.f;
#pragma unroll
        for (int nt = 0; nt < 8; nt++) {
            s[nt][0] = __expf(s[nt][0] - mn0);
            s[nt][1] = __expf(s[nt][1] - mn0);
            s[nt][2] = __expf(s[nt][2] - mn1);
            s[nt][3] = __expf(s[nt][3] - mn1);
            sum0 += s[nt][0] + s[nt][1];
            sum1 += s[nt][2] + s[nt][3];
        }
        sum0 += __shfl_xor_sync(0xffffffffu, sum0, 1);
        sum0 += __shfl_xor_sync(0xffffffffu, sum0, 2);
        sum1 += __shfl_xor_sync(0xffffffffu, sum1, 1);
        sum1 += __shfl_xor_sync(0xffffffffu, sum1, 2);
        l0 = l0 * c0 + sum0;
        l1 = l1 * c1 + sum1;

#pragma unroll
        for (int nt = 0; nt < 16; nt++) {
            o[nt][0] *= c0; o[nt][1] *= c0;
            o[nt][2] *= c1; o[nt][3] *= c1;
        }

        __syncthreads();

#pragma unroll
        for (int nt = 0; nt < 8; nt++) {
            Ps[row0 * 36 + nt * 4 + t]       = pack_h2(s[nt][0], s[nt][1]);
            Ps[(row0 + 8) * 36 + nt * 4 + t] = pack_h2(s[nt][2], s[nt][3]);
        }
        __syncwarp();

#pragma unroll
        for (int ks = 0; ks < 4; ks++) {
            const unsigned* pp = Ps + row0 * 36 + ks * 8;
            unsigned a[4] = {pp[t], pp[8 * 36 + t], pp[t + 4], pp[8 * 36 + t + 4]};
#pragma unroll
            for (int nt = 0; nt < 16; nt++) {
                const unsigned* vp = Vp + (ks * 8 + t) * 136 + nt * 8 + g;
                unsigned bb[2] = {vp[0], vp[4 * 136]};
                mma_f16(o[nt], a, bb);
            }
        }
    }

    const float inv0 = 1.f / l0, inv1 = 1.f / l1;
    __half* outr0 = g_A2h + (size_t)(t0 + row0) * DDIM + n * HD;
    __half* outr1 = g_A2h + (size_t)(t0 + row0 + 8) * DDIM + n * HD;
#pragma unroll
    for (int nt = 0; nt < 16; nt++) {
        const int col = nt * 8 + 2 * t;
        *(__half2*)(outr0 + col) = __floats2half2_rn(o[nt][0] * inv0, o[nt][1] * inv0);
        *(__half2*)(outr1 + col) = __floats2half2_rn(o[nt][2] * inv1, o[nt][3] * inv1);
    }
}

// ---------------- kernel 4: output projection ------------------------------
__global__ __launch_bounds__(128) void k_gemm_o(float* __restrict__ out_o)
{
    gemm_mma128_h(g_A2h, DDIM, g_Wp + WOP_OFF + (size_t)blockIdx.x * 128, DDIM,
                  out_o + (size_t)blockIdx.x * 128, DDIM,
                  DDIM, blockIdx.y * 128);
}

// ---------------- launch ----------------------------------------------------
extern "C" void kernel_launch(void* const* d_in, const int* in_sizes, int n_in,
                              void* d_out, int out_size)
{
    (void)in_sizes; (void)n_in; (void)out_size;
    const float* x     = (const float*)d_in[0];
    const float* wq    = (const float*)d_in[1];
    const float* wk    = (const float*)d_in[2];
    const float* wv    = (const float*)d_in[3];
    const float* wo    = (const float*)d_in[4];
    const float* kc_in = (const float*)d_in[5];
    const float* vc_in = (const float*)d_in[6];
    const int* positions = (const int*)d_in[7];
    const int* widx      = (const int*)d_in[8];

    float* out_kc = (float*)d_out;
    float* out_vc = out_kc + (size_t)NSLOTS * NKV * HD;
    float* out_o  = out_vc + (size_t)NSLOTS * NKV * HD;

    static cudaStream_t s2 = nullptr;
    static cudaEvent_t  e1 = nullptr, e2 = nullptr;
    if (!s2) {
        cudaStreamCreateWithFlags(&s2, cudaStreamNonBlocking);
        cudaEventCreateWithFlags(&e1, cudaEventDisableTiming);
        cudaEventCreateWithFlags(&e2, cudaEventDisableTiming);
    }

    const size_t cacheBytes = (size_t)NSLOTS * NKV * HD * sizeof(float);

    // fork: cache copies on s2, concurrent with prep + QKV GEMM
    cudaEventRecord(e1, 0);
    cudaStreamWaitEvent(s2, e1, 0);
    cudaMemcpyAsync(out_kc, kc_in, cacheBytes, cudaMemcpyDeviceToDevice, s2);
    cudaMemcpyAsync(out_vc, vc_in, cacheBytes, cudaMemcpyDeviceToDevice, s2);
    cudaEventRecord(e2, s2);

    // ---- prep: x -> fp16; weights -> packed half2 (along K) ----
    __half* gXh;   cudaGetSymbolAddress((void**)&gXh, g_Xh);
    unsigned* gWp; cudaGetSymbolAddress((void**)&gWp, g_Wp);
    {
        int n4 = (int)((size_t)TSEQ * DDIM / 4);
        k_cvt_half<<<(n4 + 255) / 256, 256>>>((const float4*)x, (uint2*)gXh, n4);

        int nq = (int)WQP_ELEMS;
        k_pack_half<<<(nq + 255) / 256, 256>>>(wq, gWp + WQP_OFF,
                                               NQ * (DDIM / 2), HD);
        int nk = (int)WKP_ELEMS;
        k_pack_half<<<(nk + 255) / 256, 256>>>(wk, gWp + WKP_OFF,
                                               NKV * (DDIM / 2), HD);
        k_pack_half<<<(nk + 255) / 256, 256>>>(wv, gWp + WVP_OFF,
                                               NKV * (DDIM / 2), HD);
        int no = (int)WOP_ELEMS;
        k_pack_half<<<(no + 255) / 256, 256>>>(wo, gWp + WOP_OFF,
                                               DDIM / 2, DDIM);
    }

    k_gemm_qkv<<<dim3(48, TSEQ / 128), 128, 0, 0>>>();

    // join: rope overwrites cache rows, must follow the copies
    cudaStreamWaitEvent(0, e2, 0);
    k_rope<<<TSEQ, 256, 0, 0>>>(positions, widx, out_kc, out_vc);

    const int attn_smem = ATTN3_SMEM_WORDS * (int)sizeof(unsigned);
    cudaFuncSetAttribute(k_attn_h,
                         cudaFuncAttributeMaxDynamicSharedMemorySize, attn_smem);
    k_attn_h<<<dim3(TSEQ / 64, NQ), 128, attn_smem, 0>>>(positions);

    k_gemm_o<<<dim3(DDIM / 128, TSEQ / 128), 128, 0, 0>>>(out_o);
}

// round 13
// speedup vs baseline: 1.0771x; 1.0771x over previous
#include <cuda_runtime.h>
#include <cuda_fp16.h>
#include <cstdint>
#include <stdint.h>
#include <math.h>

// Problem constants (fixed by the dataset)
#define TSEQ   2048
#define DDIM   4096
#define NQ     32
#define NKV    8
#define HD     128
#define NSLOTS 32768
#define QKVC   6144   // 32*128 + 8*128 + 8*128

// Packed-weight offsets (uint = half2 elements), pack along K
#define WQP_ELEMS ((size_t)NQ  * (DDIM / 2) * HD)
#define WKP_ELEMS ((size_t)NKV * (DDIM / 2) * HD)
#define WOP_ELEMS ((size_t)(DDIM / 2) * DDIM)
#define WQP_OFF   ((size_t)0)
#define WKP_OFF   (WQP_OFF + WQP_ELEMS)
#define WVP_OFF   (WKP_OFF + WKP_ELEMS)
#define WOP_OFF   (WVP_OFF + WKP_ELEMS)

// ---------------- scratch (static device allocations; no cudaMalloc) -------
__device__ float    g_QKV[(size_t)TSEQ * QKVC];      // [t][6144] fp32
__device__ __half   g_Qh [(size_t)NQ  * TSEQ * HD];  // [n][t][h] fp16 (scaled)
__device__ __half   g_Kh [(size_t)NKV * TSEQ * HD];  // [kh][t][h] fp16
__device__ unsigned g_Vp [(size_t)NKV * (TSEQ / 2) * HD]; // key-pair half2
__device__ __half   g_A2h[(size_t)TSEQ * DDIM];      // [t][n*128+h] fp16
__device__ __half   g_Xh [(size_t)TSEQ * DDIM];      // x fp16 (A-side)
__device__ unsigned g_Wp [WOP_OFF + WOP_ELEMS];      // packed half2 weights

// ---------------- mma helpers -----------------------------------------------
__device__ __forceinline__ void mma_f16(float* d, const unsigned* a,
                                        const unsigned* b) {
    asm volatile(
        "mma.sync.aligned.m16n8k16.row.col.f32.f16.f16.f32 "
        "{%0,%1,%2,%3}, {%4,%5,%6,%7}, {%8,%9}, {%0,%1,%2,%3};"
        : "+f"(d[0]), "+f"(d[1]), "+f"(d[2]), "+f"(d[3])
        : "r"(a[0]), "r"(a[1]), "r"(a[2]), "r"(a[3]), "r"(b[0]), "r"(b[1]));
}

__device__ __forceinline__ void cp16(unsigned smem, const void* g) {
    asm volatile("cp.async.cg.shared.global [%0], [%1], 16;\n"
                 :: "r"(smem), "l"(g));
}

__device__ __forceinline__ unsigned pack_h2(float a, float b) {
    __half2 h = __floats2half2_rn(a, b);
    return *(unsigned*)&h;
}

// ---------------- prep kernels ---------------------------------------------
__global__ __launch_bounds__(256) void k_cvt_half(
    const float4* __restrict__ in, uint2* __restrict__ out, int n4)
{
    int i = blockIdx.x * 256 + threadIdx.x;
    if (i < n4) {
        float4 v = in[i];
        uint2 o = {pack_h2(v.x, v.y), pack_h2(v.z, v.w)};
        out[i] = o;
    }
}

__global__ __launch_bounds__(256) void k_pack_half(
    const float* __restrict__ in, unsigned* __restrict__ out, int K2, int N)
{
    int i = blockIdx.x * 256 + threadIdx.x;
    if (i < K2 * N) {
        int k2 = i / N, n = i - k2 * N;
        out[i] = pack_h2(in[(size_t)(2 * k2) * N + n],
                         in[(size_t)(2 * k2 + 1) * N + n]);
    }
}

// ---------------- 128x128 fp16 GEMM, 4 warps, 64x64 warp tile --------------
// (R10 configuration: fp32 accumulators, 3-stage single-sync pipeline)
__device__ __forceinline__ void gemm_mma128_h(
    const __half* __restrict__ A, int lda,
    const unsigned* __restrict__ Bp, int ldbp,
    float* __restrict__ C, int ldc,
    int Kdim, int rowBase)
{
    __shared__ unsigned As[3][128][20];
    __shared__ unsigned Bs[3][16][136];

    const int tid  = threadIdx.x;
    const int lane = tid & 31;
    const int warp = tid >> 5;
    const int wM   = warp >> 1;
    const int wN   = warp & 1;
    const int g    = lane >> 2;
    const int t    = lane & 3;

    const int ar = tid >> 2, ac = (tid & 3) << 2;
    const int br = tid >> 5, bc = (tid & 31) << 2;

    const __half* Ab = A + (size_t)rowBase * lda;

    float acc[4][8][4];
#pragma unroll
    for (int mt = 0; mt < 4; mt++)
#pragma unroll
        for (int nt = 0; nt < 8; nt++)
#pragma unroll
            for (int i = 0; i < 4; i++) acc[mt][nt][i] = 0.f;

    const unsigned sA0 = (unsigned)__cvta_generic_to_shared(&As[0][0][0]);
    const unsigned sB0 = (unsigned)__cvta_generic_to_shared(&Bs[0][0][0]);
    const unsigned stASz = (unsigned)(128 * 20 * 4);
    const unsigned stBSz = (unsigned)(16 * 136 * 4);

    const int niter = Kdim >> 5;

#pragma unroll
    for (int p = 0; p < 2; p++) {
        const int k0 = p << 5;
        const int k20 = k0 >> 1;
        const unsigned stA = sA0 + (unsigned)p * stASz;
        const unsigned stB = sB0 + (unsigned)p * stBSz;
#pragma unroll
        for (int q = 0; q < 4; q++) {
            cp16(stA + (unsigned)((ar + q * 32) * 20 + ac) * 4u,
                 Ab + (size_t)(ar + q * 32) * lda + k0 + ac * 2);
            cp16(stB + (unsigned)((br + q * 4) * 136 + bc) * 4u,
                 Bp + (size_t)(k20 + br + q * 4) * ldbp + bc);
        }
        asm volatile("cp.async.commit_group;");
    }

    for (int it = 0; it < niter; it++) {
        asm volatile("cp.async.wait_group 1;");
        __syncthreads();

        if (it + 2 < niter) {
            const int k0 = (it + 2) << 5;
            const int k20 = k0 >> 1;
            const int bsel = (it + 2) % 3;
            const unsigned stA = sA0 + (unsigned)bsel * stASz;
            const unsigned stB = sB0 + (unsigned)bsel * stBSz;
#pragma unroll
            for (int q = 0; q < 4; q++) {
                cp16(stA + (unsigned)((ar + q * 32) * 20 + ac) * 4u,
                     Ab + (size_t)(ar + q * 32) * lda + k0 + ac * 2);
                cp16(stB + (unsigned)((br + q * 4) * 136 + bc) * 4u,
                     Bp + (size_t)(k20 + br + q * 4) * ldbp + bc);
            }
        }
        asm volatile("cp.async.commit_group;");

        const int st = it % 3;
#pragma unroll
        for (int ks = 0; ks < 2; ks++) {
            unsigned af[4][4], bf[8][2];
#pragma unroll
            for (int mt = 0; mt < 4; mt++) {
                const unsigned* p = &As[st][wM * 64 + mt * 16 + g][ks * 8 + t];
                af[mt][0] = p[0];
                af[mt][1] = p[8 * 20];
                af[mt][2] = p[4];
                af[mt][3] = p[8 * 20 + 4];
            }
#pragma unroll
            for (int nt = 0; nt < 8; nt++) {
                bf[nt][0] = Bs[st][ks * 8 + t    ][wN * 64 + nt * 8 + g];
                bf[nt][1] = Bs[st][ks * 8 + t + 4][wN * 64 + nt * 8 + g];
            }
#pragma unroll
            for (int mt = 0; mt < 4; mt++)
#pragma unroll
                for (int nt = 0; nt < 8; nt++)
                    mma_f16(acc[mt][nt], af[mt], bf[nt]);
        }
    }

#pragma unroll
    for (int mt = 0; mt < 4; mt++) {
#pragma unroll
        for (int nt = 0; nt < 8; nt++) {
            const int r0 = rowBase + wM * 64 + mt * 16 + g;
            const int c0 = wN * 64 + nt * 8 + 2 * t;
            float2 v0 = {acc[mt][nt][0], acc[mt][nt][1]};
            float2 v1 = {acc[mt][nt][2], acc[mt][nt][3]};
            *(float2*)(C + (size_t)r0 * ldc + c0)       = v0;
            *(float2*)(C + (size_t)(r0 + 8) * ldc + c0) = v1;
        }
    }
}

// ---------------- kernel 1: fused QKV projection ---------------------------
__global__ __launch_bounds__(128) void k_gemm_qkv()
{
    int cb = blockIdx.x;
    const unsigned* Bp;
    if (cb < 32)      Bp = g_Wp + WQP_OFF + (size_t)cb * (DDIM / 2) * HD;
    else if (cb < 40) Bp = g_Wp + WKP_OFF + (size_t)(cb - 32) * (DDIM / 2) * HD;
    else              Bp = g_Wp + WVP_OFF + (size_t)(cb - 40) * (DDIM / 2) * HD;
    gemm_mma128_h(g_Xh, DDIM, Bp, HD, g_QKV + (size_t)cb * HD, QKVC,
                  DDIM, blockIdx.y * 128);
}

// ---------------- kernel 2: RoPE + fp16 split + cache writeback ------------
__global__ __launch_bounds__(256) void k_rope(
    const int* __restrict__ positions,
    const int* __restrict__ widx,
    float* __restrict__ out_kc,
    float* __restrict__ out_vc)
{
    const int t = blockIdx.x;
    __shared__ float cs[64], sn[64];
    const int pos = positions[t];
    if (threadIdx.x < 64) {
        int i = threadIdx.x;
        double e = -((double)(2 * i) / 128.0);
        float inv = (float)pow(500000.0, e);
        float ang = (float)pos * inv;
        float s, c;
        sincosf(ang, &s, &c);
        cs[i] = c;
        sn[i] = s;
    }
    __syncthreads();

    const float* row = g_QKV + (size_t)t * QKVC;
    const int wi = widx[t];
    const float qscale = 0.08838834764831845f;  // 128^-0.5

    for (int idx = threadIdx.x; idx < NQ * 64; idx += blockDim.x) {
        int n = idx >> 6, i = idx & 63;
        float x1 = row[n * HD + i];
        float x2 = row[n * HD + 64 + i];
        float c = cs[i], s = sn[i];
        __half* qd = g_Qh + ((size_t)n * TSEQ + t) * HD;
        qd[i]      = __float2half((x1 * c - x2 * s) * qscale);
        qd[64 + i] = __float2half((x2 * c + x1 * s) * qscale);
    }
    for (int idx = threadIdx.x; idx < NKV * 64; idx += blockDim.x) {
        int kh = idx >> 6, i = idx & 63;
        float x1 = row[NQ * HD + kh * HD + i];
        float x2 = row[NQ * HD + kh * HD + 64 + i];
        float c = cs[i], s = sn[i];
        float o1 = x1 * c - x2 * s;
        float o2 = x2 * c + x1 * s;
        __half* kd = g_Kh + ((size_t)kh * TSEQ + t) * HD;
        kd[i] = __float2half(o1); kd[64 + i] = __float2half(o2);
        float* kc = out_kc + ((size_t)wi * NKV + kh) * HD;
        kc[i] = o1; kc[64 + i] = o2;    // cache stays exact fp32
    }
    for (int idx = threadIdx.x; idx < NKV * HD; idx += blockDim.x) {
        int kh = idx >> 7, h = idx & 127;
        float v = row[(NQ + NKV) * HD + kh * HD + h];
        __half* vh = (__half*)g_Vp;
        vh[(((size_t)kh * (TSEQ / 2) + (t >> 1)) * HD + h) * 2 + (t & 1)] =
            __float2half(v);
        out_vc[((size_t)wi * NKV + kh) * HD + h] = v;   // exact fp32
    }
}

// ---------------- kernel 3: fp16-mma causal flash attention ----------------
// bx0: query-block offset (kernel split for overlap with k_gemm_o).
#define ATTN3_SMEM_WORDS (4352 * 3 + 64)
__global__ __launch_bounds__(128) void k_attn_h(const int* __restrict__ positions,
                                                int bx0)
{
    extern __shared__ unsigned smw[];
    unsigned* Qs  = smw;
    unsigned* Ks  = smw + 4352;
    unsigned* Vp  = smw + 8704;
    int*      PKs = (int*)(smw + 13056);
    unsigned* Ps  = Ks;               // alias (Ks dead once S is computed)

    const int n    = blockIdx.y;
    const int kh   = n >> 2;
    const int bx   = blockIdx.x + bx0;
    const int t0   = bx * 64;
    const int tid  = threadIdx.x;
    const int lane = tid & 31;
    const int w    = tid >> 5;
    const int g    = lane >> 2;
    const int t    = lane & 3;

    const unsigned* Qg = (const unsigned*)(g_Qh + ((size_t)n * TSEQ + t0) * HD);
    for (int i = tid; i < 1024; i += 128) {
        int r = i >> 4, c = (i & 15) << 2;
        *(uint4*)(Qs + r * 68 + c) = *(const uint4*)(Qg + (size_t)r * 64 + c);
    }

    const int row0 = w * 16 + g;
    const int pq0 = positions[t0 + row0];
    const int pq1 = positions[t0 + row0 + 8];

    float m0 = -1e30f, m1 = -1e30f, l0 = 0.f, l1 = 0.f;
    float o[16][4];
#pragma unroll
    for (int nt = 0; nt < 16; nt++)
#pragma unroll
        for (int i = 0; i < 4; i++) o[nt][i] = 0.f;

    const unsigned* Kg = (const unsigned*)(g_Kh + (size_t)kh * TSEQ * HD);
    const unsigned* Vg = g_Vp + (size_t)kh * (TSEQ / 2) * HD;

    const int nchunks = bx + 1;
    for (int ch = 0; ch < nchunks; ch++) {
        const int s0 = ch * 64;
        __syncthreads();

        for (int i = tid; i < 1024; i += 128) {
            int r = i >> 4, c = (i & 15) << 2;
            *(uint4*)(Ks + r * 68 + c) =
                *(const uint4*)(Kg + (size_t)(s0 + r) * 64 + c);
        }
        for (int i = tid; i < 1024; i += 128) {
            int r2 = i >> 5, c = (i & 31) << 2;
            *(uint4*)(Vp + r2 * 136 + c) =
                *(const uint4*)(Vg + (size_t)(s0 / 2 + r2) * HD + c);
        }
        if (tid < 64) PKs[tid] = positions[s0 + tid];
        __syncthreads();

        float s[8][4];
#pragma unroll
        for (int nt = 0; nt < 8; nt++)
#pragma unroll
            for (int i = 0; i < 4; i++) s[nt][i] = 0.f;

#pragma unroll
        for (int ks = 0; ks < 8; ks++) {
            const unsigned* qp = Qs + row0 * 68 + ks * 8;
            unsigned a[4] = {qp[t], qp[8 * 68 + t], qp[t + 4], qp[8 * 68 + t + 4]};
#pragma unroll
            for (int nt = 0; nt < 8; nt++) {
                const unsigned* kp = Ks + (nt * 8 + g) * 68 + ks * 8;
                unsigned bb[2] = {kp[t], kp[t + 4]};
                mma_f16(s[nt], a, bb);
            }
        }

        float mx0 = -1e30f, mx1 = -1e30f;
#pragma unroll
        for (int nt = 0; nt < 8; nt++) {
            const int col = nt * 8 + 2 * t;
            int2 pk = *(const int2*)(PKs + col);
            if (pq0 < pk.x) s[nt][0] = -1e30f;
            if (pq0 < pk.y) s[nt][1] = -1e30f;
            if (pq1 < pk.x) s[nt][2] = -1e30f;
            if (pq1 < pk.y) s[nt][3] = -1e30f;
            mx0 = fmaxf(mx0, fmaxf(s[nt][0], s[nt][1]));
            mx1 = fmaxf(mx1, fmaxf(s[nt][2], s[nt][3]));
        }
        mx0 = fmaxf(mx0, __shfl_xor_sync(0xffffffffu, mx0, 1));
        mx0 = fmaxf(mx0, __shfl_xor_sync(0xffffffffu, mx0, 2));
        mx1 = fmaxf(mx1, __shfl_xor_sync(0xffffffffu, mx1, 1));
        mx1 = fmaxf(mx1, __shfl_xor_sync(0xffffffffu, mx1, 2));

        const float mn0 = fmaxf(m0, mx0), mn1 = fmaxf(m1, mx1);
        const float c0 = __expf(m0 - mn0), c1 = __expf(m1 - mn1);
        m0 = mn0; m1 = mn1;

        float sum0 = 0.f, sum1 = 0.f;
#pragma unroll
        for (int nt = 0; nt < 8; nt++) {
            s[nt][0] = __expf(s[nt][0] - mn0);
            s[nt][1] = __expf(s[nt][1] - mn0);
            s[nt][2] = __expf(s[nt][2] - mn1);
            s[nt][3] = __expf(s[nt][3] - mn1);
            sum0 += s[nt][0] + s[nt][1];
            sum1 += s[nt][2] + s[nt][3];
        }
        sum0 += __shfl_xor_sync(0xffffffffu, sum0, 1);
        sum0 += __shfl_xor_sync(0xffffffffu, sum0, 2);
        sum1 += __shfl_xor_sync(0xffffffffu, sum1, 1);
        sum1 += __shfl_xor_sync(0xffffffffu, sum1, 2);
        l0 = l0 * c0 + sum0;
        l1 = l1 * c1 + sum1;

#pragma unroll
        for (int nt = 0; nt < 16; nt++) {
            o[nt][0] *= c0; o[nt][1] *= c0;
            o[nt][2] *= c1; o[nt][3] *= c1;
        }

        __syncthreads();

#pragma unroll
        for (int nt = 0; nt < 8; nt++) {
            Ps[row0 * 36 + nt * 4 + t]       = pack_h2(s[nt][0], s[nt][1]);
            Ps[(row0 + 8) * 36 + nt * 4 + t] = pack_h2(s[nt][2], s[nt][3]);
        }
        __syncwarp();

#pragma unroll
        for (int ks = 0; ks < 4; ks++) {
            const unsigned* pp = Ps + row0 * 36 + ks * 8;
            unsigned a[4] = {pp[t], pp[8 * 36 + t], pp[t + 4], pp[8 * 36 + t + 4]};
#pragma unroll
            for (int nt = 0; nt < 16; nt++) {
                const unsigned* vp = Vp + (ks * 8 + t) * 136 + nt * 8 + g;
                unsigned bb[2] = {vp[0], vp[4 * 136]};
                mma_f16(o[nt], a, bb);
            }
        }
    }

    const float inv0 = 1.f / l0, inv1 = 1.f / l1;
    __half* outr0 = g_A2h + (size_t)(t0 + row0) * DDIM + n * HD;
    __half* outr1 = g_A2h + (size_t)(t0 + row0 + 8) * DDIM + n * HD;
#pragma unroll
    for (int nt = 0; nt < 16; nt++) {
        const int col = nt * 8 + 2 * t;
        *(__half2*)(outr0 + col) = __floats2half2_rn(o[nt][0] * inv0, o[nt][1] * inv0);
        *(__half2*)(outr1 + col) = __floats2half2_rn(o[nt][2] * inv1, o[nt][3] * inv1);
    }
}

// ---------------- kernel 4: output projection (row-split for overlap) ------
__global__ __launch_bounds__(128) void k_gemm_o(float* __restrict__ out_o,
                                                int rowBlk0)
{
    gemm_mma128_h(g_A2h, DDIM, g_Wp + WOP_OFF + (size_t)blockIdx.x * 128, DDIM,
                  out_o + (size_t)blockIdx.x * 128, DDIM,
                  DDIM, (blockIdx.y + rowBlk0) * 128);
}

// ---------------- launch ----------------------------------------------------
extern "C" void kernel_launch(void* const* d_in, const int* in_sizes, int n_in,
                              void* d_out, int out_size)
{
    (void)in_sizes; (void)n_in; (void)out_size;
    const float* x     = (const float*)d_in[0];
    const float* wq    = (const float*)d_in[1];
    const float* wk    = (const float*)d_in[2];
    const float* wv    = (const float*)d_in[3];
    const float* wo    = (const float*)d_in[4];
    const float* kc_in = (const float*)d_in[5];
    const float* vc_in = (const float*)d_in[6];
    const int* positions = (const int*)d_in[7];
    const int* widx      = (const int*)d_in[8];

    float* out_kc = (float*)d_out;
    float* out_vc = out_kc + (size_t)NSLOTS * NKV * HD;
    float* out_o  = out_vc + (size_t)NSLOTS * NKV * HD;

    static cudaStream_t s2 = nullptr;
    static cudaEvent_t  e1 = nullptr, e2 = nullptr, eA = nullptr, eOA = nullptr;
    if (!s2) {
        cudaStreamCreateWithFlags(&s2, cudaStreamNonBlocking);
        cudaEventCreateWithFlags(&e1, cudaEventDisableTiming);
        cudaEventCreateWithFlags(&e2, cudaEventDisableTiming);
        cudaEventCreateWithFlags(&eA, cudaEventDisableTiming);
        cudaEventCreateWithFlags(&eOA, cudaEventDisableTiming);
    }

    const size_t cacheBytes = (size_t)NSLOTS * NKV * HD * sizeof(float);

    __half* gXh;   cudaGetSymbolAddress((void**)&gXh, g_Xh);
    unsigned* gWp; cudaGetSymbolAddress((void**)&gWp, g_Wp);

    // fork: cache copies + wo pack on s2 (off the qkv critical path)
    cudaEventRecord(e1, 0);
    cudaStreamWaitEvent(s2, e1, 0);
    cudaMemcpyAsync(out_kc, kc_in, cacheBytes, cudaMemcpyDeviceToDevice, s2);
    cudaMemcpyAsync(out_vc, vc_in, cacheBytes, cudaMemcpyDeviceToDevice, s2);
    cudaEventRecord(e2, s2);
    {
        int no = (int)WOP_ELEMS;
        k_pack_half<<<(no + 255) / 256, 256, 0, s2>>>(wo, gWp + WOP_OFF,
                                                      DDIM / 2, DDIM);
    }

    // stream 0: critical-path prep (x + q/k/v weights), then QKV GEMM
    {
        int n4 = (int)((size_t)TSEQ * DDIM / 4);
        k_cvt_half<<<(n4 + 255) / 256, 256>>>((const float4*)x, (uint2*)gXh, n4);

        int nq = (int)WQP_ELEMS;
        k_pack_half<<<(nq + 255) / 256, 256>>>(wq, gWp + WQP_OFF,
                                               NQ * (DDIM / 2), HD);
        int nk = (int)WKP_ELEMS;
        k_pack_half<<<(nk + 255) / 256, 256>>>(wk, gWp + WKP_OFF,
                                               NKV * (DDIM / 2), HD);
        k_pack_half<<<(nk + 255) / 256, 256>>>(wv, gWp + WVP_OFF,
                                               NKV * (DDIM / 2), HD);
    }

    k_gemm_qkv<<<dim3(48, TSEQ / 128), 128, 0, 0>>>();

    // join: rope overwrites cache rows, must follow the copies
    cudaStreamWaitEvent(0, e2, 0);
    k_rope<<<TSEQ, 256, 0, 0>>>(positions, widx, out_kc, out_vc);

    const int attn_smem = ATTN3_SMEM_WORDS * (int)sizeof(unsigned);
    cudaFuncSetAttribute(k_attn_h,
                         cudaFuncAttributeMaxDynamicSharedMemorySize, attn_smem);

    // attention split: light half (bx 0..15), then heavy half (bx 16..31).
    k_attn_h<<<dim3(16, NQ), 128, attn_smem, 0>>>(positions, 0);
    cudaEventRecord(eA, 0);
    k_attn_h<<<dim3(16, NQ), 128, attn_smem, 0>>>(positions, 16);

    // gemm_o rows 0..1023 depends only on attnA -> run on s2, overlapping attnB
    cudaStreamWaitEvent(s2, eA, 0);
    k_gemm_o<<<dim3(DDIM / 128, 8), 128, 0, s2>>>(out_o, 0);
    cudaEventRecord(eOA, s2);

    // gemm_o rows 1024..2047 after attnB on stream 0; then join s2
    k_gemm_o<<<dim3(DDIM / 128, 8), 128, 0, 0>>>(out_o, 8);
    cudaStreamWaitEvent(0, eOA, 0);
}

// round 15
// speedup vs baseline: 1.1042x; 1.0252x over previous
#include <cuda_runtime.h>
#include <cuda_fp16.h>
#include <cstdint>
#include <stdint.h>
#include <math.h>

// Problem constants (fixed by the dataset)
#define TSEQ   2048
#define DDIM   4096
#define NQ     32
#define NKV    8
#define HD     128
#define NSLOTS 32768
#define QKVC   6144   // 32*128 + 8*128 + 8*128

// Packed-weight offsets (uint = half2 elements), pack along K
#define WQP_ELEMS ((size_t)NQ  * (DDIM / 2) * HD)
#define WKP_ELEMS ((size_t)NKV * (DDIM / 2) * HD)
#define WOP_ELEMS ((size_t)(DDIM / 2) * DDIM)
#define WQP_OFF   ((size_t)0)
#define WKP_OFF   (WQP_OFF + WQP_ELEMS)
#define WVP_OFF   (WKP_OFF + WKP_ELEMS)
#define WOP_OFF   (WVP_OFF + WKP_ELEMS)

// ---------------- scratch (static device allocations; no cudaMalloc) -------
__device__ float    g_QKV[(size_t)TSEQ * QKVC];      // [t][6144] fp32
__device__ __half   g_Qh [(size_t)NQ  * TSEQ * HD];  // [n][t][h] fp16 (scaled)
__device__ __half   g_Kh [(size_t)NKV * TSEQ * HD];  // [kh][t][h] fp16
__device__ unsigned g_Vp [(size_t)NKV * (TSEQ / 2) * HD]; // key-pair half2
__device__ __half   g_A2h[(size_t)TSEQ * DDIM];      // [t][n*128+h] fp16
__device__ __half   g_Xh [(size_t)TSEQ * DDIM];      // x fp16 (A-side)
__device__ unsigned g_Wp [WOP_OFF + WOP_ELEMS];      // packed half2 weights

// ---------------- mma helpers -----------------------------------------------
__device__ __forceinline__ void mma_f16(float* d, const unsigned* a,
                                        const unsigned* b) {
    asm volatile(
        "mma.sync.aligned.m16n8k16.row.col.f32.f16.f16.f32 "
        "{%0,%1,%2,%3}, {%4,%5,%6,%7}, {%8,%9}, {%0,%1,%2,%3};"
        : "+f"(d[0]), "+f"(d[1]), "+f"(d[2]), "+f"(d[3])
        : "r"(a[0]), "r"(a[1]), "r"(a[2]), "r"(a[3]), "r"(b[0]), "r"(b[1]));
}

__device__ __forceinline__ void cp16(unsigned smem, const void* g) {
    asm volatile("cp.async.cg.shared.global [%0], [%1], 16;\n"
                 :: "r"(smem), "l"(g));
}

__device__ __forceinline__ unsigned pack_h2(float a, float b) {
    __half2 h = __floats2half2_rn(a, b);
    return *(unsigned*)&h;
}

// ---------------- prep kernels ---------------------------------------------
__global__ __launch_bounds__(256) void k_cvt_half(
    const float4* __restrict__ in, uint2* __restrict__ out, int n4)
{
    int i = blockIdx.x * 256 + threadIdx.x;
    if (i < n4) {
        float4 v = in[i];
        uint2 o = {pack_h2(v.x, v.y), pack_h2(v.z, v.w)};
        out[i] = o;
    }
}

__global__ __launch_bounds__(256) void k_pack_half(
    const float* __restrict__ in, unsigned* __restrict__ out, int K2, int N)
{
    int i = blockIdx.x * 256 + threadIdx.x;
    if (i < K2 * N) {
        int k2 = i / N, n = i - k2 * N;
        out[i] = pack_h2(in[(size_t)(2 * k2) * N + n],
                         in[(size_t)(2 * k2 + 1) * N + n]);
    }
}

// ---------------- 128x128 fp16 GEMM, 4 warps, 64x64 warp tile --------------
// 2-stage cp.async pipeline (37.9 KB smem) so 3 CTAs/SM fit (12 warps/SM,
// 3 warps/SMSP of HMMA issue pressure). fp32 accumulators (R10 numerics).
__device__ __forceinline__ void gemm_mma128_h(
    const __half* __restrict__ A, int lda,
    const unsigned* __restrict__ Bp, int ldbp,
    float* __restrict__ C, int ldc,
    int Kdim, int rowBase)
{
    __shared__ unsigned As[2][128][20];
    __shared__ unsigned Bs[2][16][136];

    const int tid  = threadIdx.x;
    const int lane = tid & 31;
    const int warp = tid >> 5;
    const int wM   = warp >> 1;
    const int wN   = warp & 1;
    const int g    = lane >> 2;
    const int t    = lane & 3;

    const int ar = tid >> 2, ac = (tid & 3) << 2;
    const int br = tid >> 5, bc = (tid & 31) << 2;

    const __half* Ab = A + (size_t)rowBase * lda;

    float acc[4][8][4];
#pragma unroll
    for (int mt = 0; mt < 4; mt++)
#pragma unroll
        for (int nt = 0; nt < 8; nt++)
#pragma unroll
            for (int i = 0; i < 4; i++) acc[mt][nt][i] = 0.f;

    const unsigned sA0 = (unsigned)__cvta_generic_to_shared(&As[0][0][0]);
    const unsigned sB0 = (unsigned)__cvta_generic_to_shared(&Bs[0][0][0]);
    const unsigned stASz = (unsigned)(128 * 20 * 4);
    const unsigned stBSz = (unsigned)(16 * 136 * 4);

    const int niter = Kdim >> 5;

    // prologue: stage 0
    {
        const unsigned stA = sA0;
        const unsigned stB = sB0;
#pragma unroll
        for (int q = 0; q < 4; q++) {
            cp16(stA + (unsigned)((ar + q * 32) * 20 + ac) * 4u,
                 Ab + (size_t)(ar + q * 32) * lda + ac * 2);
            cp16(stB + (unsigned)((br + q * 4) * 136 + bc) * 4u,
                 Bp + (size_t)(br + q * 4) * ldbp + bc);
        }
        asm volatile("cp.async.commit_group;");
    }

    for (int it = 0; it < niter; it++) {
        if (it + 1 < niter) {
            const int k0 = (it + 1) << 5;
            const int k20 = k0 >> 1;
            const int bsel = (it + 1) & 1;
            const unsigned stA = sA0 + (unsigned)bsel * stASz;
            const unsigned stB = sB0 + (unsigned)bsel * stBSz;
#pragma unroll
            for (int q = 0; q < 4; q++) {
                cp16(stA + (unsigned)((ar + q * 32) * 20 + ac) * 4u,
                     Ab + (size_t)(ar + q * 32) * lda + k0 + ac * 2);
                cp16(stB + (unsigned)((br + q * 4) * 136 + bc) * 4u,
                     Bp + (size_t)(k20 + br + q * 4) * ldbp + bc);
            }
        }
        asm volatile("cp.async.commit_group;");
        asm volatile("cp.async.wait_group 1;");
        __syncthreads();

        const int st = it & 1;
#pragma unroll
        for (int ks = 0; ks < 2; ks++) {
            unsigned af[4][4], bf[8][2];
#pragma unroll
            for (int mt = 0; mt < 4; mt++) {
                const unsigned* p = &As[st][wM * 64 + mt * 16 + g][ks * 8 + t];
                af[mt][0] = p[0];
                af[mt][1] = p[8 * 20];
                af[mt][2] = p[4];
                af[mt][3] = p[8 * 20 + 4];
            }
#pragma unroll
            for (int nt = 0; nt < 8; nt++) {
                bf[nt][0] = Bs[st][ks * 8 + t    ][wN * 64 + nt * 8 + g];
                bf[nt][1] = Bs[st][ks * 8 + t + 4][wN * 64 + nt * 8 + g];
            }
#pragma unroll
            for (int mt = 0; mt < 4; mt++)
#pragma unroll
                for (int nt = 0; nt < 8; nt++)
                    mma_f16(acc[mt][nt], af[mt], bf[nt]);
        }
        __syncthreads();   // protect stage st before it+2's load overwrites
    }

#pragma unroll
    for (int mt = 0; mt < 4; mt++) {
#pragma unroll
        for (int nt = 0; nt < 8; nt++) {
            const int r0 = rowBase + wM * 64 + mt * 16 + g;
            const int c0 = wN * 64 + nt * 8 + 2 * t;
            float2 v0 = {acc[mt][nt][0], acc[mt][nt][1]};
            float2 v1 = {acc[mt][nt][2], acc[mt][nt][3]};
            *(float2*)(C + (size_t)r0 * ldc + c0)       = v0;
            *(float2*)(C + (size_t)(r0 + 8) * ldc + c0) = v1;
        }
    }
}

// ---------------- kernel 1: fused QKV projection ---------------------------
__global__ __launch_bounds__(128, 3) void k_gemm_qkv()
{
    int cb = blockIdx.x;
    const unsigned* Bp;
    if (cb < 32)      Bp = g_Wp + WQP_OFF + (size_t)cb * (DDIM / 2) * HD;
    else if (cb < 40) Bp = g_Wp + WKP_OFF + (size_t)(cb - 32) * (DDIM / 2) * HD;
    else              Bp = g_Wp + WVP_OFF + (size_t)(cb - 40) * (DDIM / 2) * HD;
    gemm_mma128_h(g_Xh, DDIM, Bp, HD, g_QKV + (size_t)cb * HD, QKVC,
                  DDIM, blockIdx.y * 128);
}

// ---------------- kernel 2: RoPE + fp16 split + cache writeback ------------
__global__ __launch_bounds__(256) void k_rope(
    const int* __restrict__ positions,
    const int* __restrict__ widx,
    float* __restrict__ out_kc,
    float* __restrict__ out_vc)
{
    const int t = blockIdx.x;
    __shared__ float cs[64], sn[64];
    const int pos = positions[t];
    if (threadIdx.x < 64) {
        int i = threadIdx.x;
        double e = -((double)(2 * i) / 128.0);
        float inv = (float)pow(500000.0, e);
        float ang = (float)pos * inv;
        float s, c;
        sincosf(ang, &s, &c);
        cs[i] = c;
        sn[i] = s;
    }
    __syncthreads();

    const float* row = g_QKV + (size_t)t * QKVC;
    const int wi = widx[t];
    const float qscale = 0.08838834764831845f;  // 128^-0.5

    for (int idx = threadIdx.x; idx < NQ * 64; idx += blockDim.x) {
        int n = idx >> 6, i = idx & 63;
        float x1 = row[n * HD + i];
        float x2 = row[n * HD + 64 + i];
        float c = cs[i], s = sn[i];
        __half* qd = g_Qh + ((size_t)n * TSEQ + t) * HD;
        qd[i]      = __float2half((x1 * c - x2 * s) * qscale);
        qd[64 + i] = __float2half((x2 * c + x1 * s) * qscale);
    }
    for (int idx = threadIdx.x; idx < NKV * 64; idx += blockDim.x) {
        int kh = idx >> 6, i = idx & 63;
        float x1 = row[NQ * HD + kh * HD + i];
        float x2 = row[NQ * HD + kh * HD + 64 + i];
        float c = cs[i], s = sn[i];
        float o1 = x1 * c - x2 * s;
        float o2 = x2 * c + x1 * s;
        __half* kd = g_Kh + ((size_t)kh * TSEQ + t) * HD;
        kd[i] = __float2half(o1); kd[64 + i] = __float2half(o2);
        float* kc = out_kc + ((size_t)wi * NKV + kh) * HD;
        kc[i] = o1; kc[64 + i] = o2;    // cache stays exact fp32
    }
    for (int idx = threadIdx.x; idx < NKV * HD; idx += blockDim.x) {
        int kh = idx >> 7, h = idx & 127;
        float v = row[(NQ + NKV) * HD + kh * HD + h];
        __half* vh = (__half*)g_Vp;
        vh[(((size_t)kh * (TSEQ / 2) + (t >> 1)) * HD + h) * 2 + (t & 1)] =
            __float2half(v);
        out_vc[((size_t)wi * NKV + kh) * HD + h] = v;   // exact fp32
    }
}

// ---------------- kernel 3: fp16-mma causal flash attention ----------------
// bx0: query-block offset (kernel split for overlap with k_gemm_o).
#define ATTN3_SMEM_WORDS (4352 * 3 + 64)
__global__ __launch_bounds__(128) void k_attn_h(const int* __restrict__ positions,
                                                int bx0)
{
    extern __shared__ unsigned smw[];
    unsigned* Qs  = smw;
    unsigned* Ks  = smw + 4352;
    unsigned* Vp  = smw + 8704;
    int*      PKs = (int*)(smw + 13056);
    unsigned* Ps  = Ks;               // alias (Ks dead once S is computed)

    const int n    = blockIdx.y;
    const int kh   = n >> 2;
    const int bx   = blockIdx.x + bx0;
    const int t0   = bx * 64;
    const int tid  = threadIdx.x;
    const int lane = tid & 31;
    const int w    = tid >> 5;
    const int g    = lane >> 2;
    const int t    = lane & 3;

    const unsigned* Qg = (const unsigned*)(g_Qh + ((size_t)n * TSEQ + t0) * HD);
    for (int i = tid; i < 1024; i += 128) {
        int r = i >> 4, c = (i & 15) << 2;
        *(uint4*)(Qs + r * 68 + c) = *(const uint4*)(Qg + (size_t)r * 64 + c);
    }

    const int row0 = w * 16 + g;
    const int pq0 = positions[t0 + row0];
    const int pq1 = positions[t0 + row0 + 8];

    float m0 = -1e30f, m1 = -1e30f, l0 = 0.f, l1 = 0.f;
    float o[16][4];
#pragma unroll
    for (int nt = 0; nt < 16; nt++)
#pragma unroll
        for (int i = 0; i < 4; i++) o[nt][i] = 0.f;

    const unsigned* Kg = (const unsigned*)(g_Kh + (size_t)kh * TSEQ * HD);
    const unsigned* Vg = g_Vp + (size_t)kh * (TSEQ / 2) * HD;

    const int nchunks = bx + 1;
    for (int ch = 0; ch < nchunks; ch++) {
        const int s0 = ch * 64;
        __syncthreads();

        for (int i = tid; i < 1024; i += 128) {
            int r = i >> 4, c = (i & 15) << 2;
            *(uint4*)(Ks + r * 68 + c) =
                *(const uint4*)(Kg + (size_t)(s0 + r) * 64 + c);
        }
        for (int i = tid; i < 1024; i += 128) {
            int r2 = i >> 5, c = (i & 31) << 2;
            *(uint4*)(Vp + r2 * 136 + c) =
                *(const uint4*)(Vg + (size_t)(s0 / 2 + r2) * HD + c);
        }
        if (tid < 64) PKs[tid] = positions[s0 + tid];
        __syncthreads();

        float s[8][4];
#pragma unroll
        for (int nt = 0; nt < 8; nt++)
#pragma unroll
            for (int i = 0; i < 4; i++) s[nt][i] = 0.f;

#pragma unroll
        for (int ks = 0; ks < 8; ks++) {
            const unsigned* qp = Qs + row0 * 68 + ks * 8;
            unsigned a[4] = {qp[t], qp[8 * 68 + t], qp[t + 4], qp[8 * 68 + t + 4]};
#pragma unroll
            for (int nt = 0; nt < 8; nt++) {
                const unsigned* kp = Ks + (nt * 8 + g) * 68 + ks * 8;
                unsigned bb[2] = {kp[t], kp[t + 4]};
                mma_f16(s[nt], a, bb);
            }
        }

        float mx0 = -1e30f, mx1 = -1e30f;
#pragma unroll
        for (int nt = 0; nt < 8; nt++) {
            const int col = nt * 8 + 2 * t;
            int2 pk = *(const int2*)(PKs + col);
            if (pq0 < pk.x) s[nt][0] = -1e30f;
            if (pq0 < pk.y) s[nt][1] = -1e30f;
            if (pq1 < pk.x) s[nt][2] = -1e30f;
            if (pq1 < pk.y) s[nt][3] = -1e30f;
            mx0 = fmaxf(mx0, fmaxf(s[nt][0], s[nt][1]));
            mx1 = fmaxf(mx1, fmaxf(s[nt][2], s[nt][3]));
        }
        mx0 = fmaxf(mx0, __shfl_xor_sync(0xffffffffu, mx0, 1));
        mx0 = fmaxf(mx0, __shfl_xor_sync(0xffffffffu, mx0, 2));
        mx1 = fmaxf(mx1, __shfl_xor_sync(0xffffffffu, mx1, 1));
        mx1 = fmaxf(mx1, __shfl_xor_sync(0xffffffffu, mx1, 2));

        const float mn0 = fmaxf(m0, mx0), mn1 = fmaxf(m1, mx1);
        const float c0 = __expf(m0 - mn0), c1 = __expf(m1 - mn1);
        m0 = mn0; m1 = mn1;

        float sum0 = 0.f, sum1 = 0.f;
#pragma unroll
        for (int nt = 0; nt < 8; nt++) {
            s[nt][0] = __expf(s[nt][0] - mn0);
            s[nt][1] = __expf(s[nt][1] - mn0);
            s[nt][2] = __expf(s[nt][2] - mn1);
            s[nt][3] = __expf(s[nt][3] - mn1);
            sum0 += s[nt][0] + s[nt][1];
            sum1 += s[nt][2] + s[nt][3];
        }
        sum0 += __shfl_xor_sync(0xffffffffu, sum0, 1);
        sum0 += __shfl_xor_sync(0xffffffffu, sum0, 2);
        sum1 += __shfl_xor_sync(0xffffffffu, sum1, 1);
        sum1 += __shfl_xor_sync(0xffffffffu, sum1, 2);
        l0 = l0 * c0 + sum0;
        l1 = l1 * c1 + sum1;

#pragma unroll
        for (int nt = 0; nt < 16; nt++) {
            o[nt][0] *= c0; o[nt][1] *= c0;
            o[nt][2] *= c1; o[nt][3] *= c1;
        }

        __syncthreads();

#pragma unroll
        for (int nt = 0; nt < 8; nt++) {
            Ps[row0 * 36 + nt * 4 + t]       = pack_h2(s[nt][0], s[nt][1]);
            Ps[(row0 + 8) * 36 + nt * 4 + t] = pack_h2(s[nt][2], s[nt][3]);
        }
        __syncwarp();

#pragma unroll
        for (int ks = 0; ks < 4; ks++) {
            const unsigned* pp = Ps + row0 * 36 + ks * 8;
            unsigned a[4] = {pp[t], pp[8 * 36 + t], pp[t + 4], pp[8 * 36 + t + 4]};
#pragma unroll
            for (int nt = 0; nt < 16; nt++) {
                const unsigned* vp = Vp + (ks * 8 + t) * 136 + nt * 8 + g;
                unsigned bb[2] = {vp[0], vp[4 * 136]};
                mma_f16(o[nt], a, bb);
            }
        }
    }

    const float inv0 = 1.f / l0, inv1 = 1.f / l1;
    __half* outr0 = g_A2h + (size_t)(t0 + row0) * DDIM + n * HD;
    __half* outr1 = g_A2h + (size_t)(t0 + row0 + 8) * DDIM + n * HD;
#pragma unroll
    for (int nt = 0; nt < 16; nt++) {
        const int col = nt * 8 + 2 * t;
        *(__half2*)(outr0 + col) = __floats2half2_rn(o[nt][0] * inv0, o[nt][1] * inv0);
        *(__half2*)(outr1 + col) = __floats2half2_rn(o[nt][2] * inv1, o[nt][3] * inv1);
    }
}

// ---------------- kernel 4: output projection (row-split for overlap) ------
__global__ __launch_bounds__(128, 3) void k_gemm_o(float* __restrict__ out_o,
                                                   int rowBlk0)
{
    gemm_mma128_h(g_A2h, DDIM, g_Wp + WOP_OFF + (size_t)blockIdx.x * 128, DDIM,
                  out_o + (size_t)blockIdx.x * 128, DDIM,
                  DDIM, (blockIdx.y + rowBlk0) * 128);
}

// ---------------- launch ----------------------------------------------------
extern "C" void kernel_launch(void* const* d_in, const int* in_sizes, int n_in,
                              void* d_out, int out_size)
{
    (void)in_sizes; (void)n_in; (void)out_size;
    const float* x     = (const float*)d_in[0];
    const float* wq    = (const float*)d_in[1];
    const float* wk    = (const float*)d_in[2];
    const float* wv    = (const float*)d_in[3];
    const float* wo    = (const float*)d_in[4];
    const float* kc_in = (const float*)d_in[5];
    const float* vc_in = (const float*)d_in[6];
    const int* positions = (const int*)d_in[7];
    const int* widx      = (const int*)d_in[8];

    float* out_kc = (float*)d_out;
    float* out_vc = out_kc + (size_t)NSLOTS * NKV * HD;
    float* out_o  = out_vc + (size_t)NSLOTS * NKV * HD;

    static cudaStream_t s2 = nullptr;
    static cudaEvent_t  e1 = nullptr, e2 = nullptr, eA = nullptr, eOA = nullptr;
    if (!s2) {
        cudaStreamCreateWithFlags(&s2, cudaStreamNonBlocking);
        cudaEventCreateWithFlags(&e1, cudaEventDisableTiming);
        cudaEventCreateWithFlags(&e2, cudaEventDisableTiming);
        cudaEventCreateWithFlags(&eA, cudaEventDisableTiming);
        cudaEventCreateWithFlags(&eOA, cudaEventDisableTiming);
    }

    const size_t cacheBytes = (size_t)NSLOTS * NKV * HD * sizeof(float);

    __half* gXh;   cudaGetSymbolAddress((void**)&gXh, g_Xh);
    unsigned* gWp; cudaGetSymbolAddress((void**)&gWp, g_Wp);

    // fork: cache copies + wo pack on s2 (off the qkv critical path)
    cudaEventRecord(e1, 0);
    cudaStreamWaitEvent(s2, e1, 0);
    cudaMemcpyAsync(out_kc, kc_in, cacheBytes, cudaMemcpyDeviceToDevice, s2);
    cudaMemcpyAsync(out_vc, vc_in, cacheBytes, cudaMemcpyDeviceToDevice, s2);
    cudaEventRecord(e2, s2);
    {
        int no = (int)WOP_ELEMS;
        k_pack_half<<<(no + 255) / 256, 256, 0, s2>>>(wo, gWp + WOP_OFF,
                                                      DDIM / 2, DDIM);
    }

    // stream 0: critical-path prep (x + q/k/v weights), then QKV GEMM
    {
        int n4 = (int)((size_t)TSEQ * DDIM / 4);
        k_cvt_half<<<(n4 + 255) / 256, 256>>>((const float4*)x, (uint2*)gXh, n4);

        int nq = (int)WQP_ELEMS;
        k_pack_half<<<(nq + 255) / 256, 256>>>(wq, gWp + WQP_OFF,
                                               NQ * (DDIM / 2), HD);
        int nk = (int)WKP_ELEMS;
        k_pack_half<<<(nk + 255) / 256, 256>>>(wk, gWp + WKP_OFF,
                                               NKV * (DDIM / 2), HD);
        k_pack_half<<<(nk + 255) / 256, 256>>>(wv, gWp + WVP_OFF,
                                               NKV * (DDIM / 2), HD);
    }

    k_gemm_qkv<<<dim3(48, TSEQ / 128), 128, 0, 0>>>();

    // join: rope overwrites cache rows, must follow the copies
    cudaStreamWaitEvent(0, e2, 0);
    k_rope<<<TSEQ, 256, 0, 0>>>(positions, widx, out_kc, out_vc);

    const int attn_smem = ATTN3_SMEM_WORDS * (int)sizeof(unsigned);
    cudaFuncSetAttribute(k_attn_h,
                         cudaFuncAttributeMaxDynamicSharedMemorySize, attn_smem);

    // attention split: light half (bx 0..15), then heavy half (bx 16..31).
    k_attn_h<<<dim3(16, NQ), 128, attn_smem, 0>>>(positions, 0);
    cudaEventRecord(eA, 0);
    k_attn_h<<<dim3(16, NQ), 128, attn_smem, 0>>>(positions, 16);

    // gemm_o rows 0..1023 depends only on attnA -> run on s2, overlapping attnB
    cudaStreamWaitEvent(s2, eA, 0);
    k_gemm_o<<<dim3(DDIM / 128, 8), 128, 0, s2>>>(out_o, 0);
    cudaEventRecord(eOA, s2);

    // gemm_o rows 1024..2047 after attnB on stream 0; then join s2
    k_gemm_o<<<dim3(DDIM / 128, 8), 128, 0, 0>>>(out_o, 8);
    cudaStreamWaitEvent(0, eOA, 0);
}